// round 3
// baseline (speedup 1.0000x reference)
#include <cuda_runtime.h>
#include <cuda_bf16.h>
#include <stdint.h>

#define B_ 8
#define I_ 16
#define C_ 256
#define P_ 4096
#define TN 64      // pixels per CTA
#define XS 264     // smem row stride (bf16) for K=256 operands
#define MS 72      // smem row stride for K=64 operand
#define NT 256

// packed A operands: uint4 per (tile,lane); tile = mt*NKT + kt
__device__ uint4 g_pWf[16 * 16 * 32];
__device__ uint4 g_pWo[16 * 16 * 32];
__device__ uint4 g_pCf[B_ * 16 * 4 * 32];  // per-b 256x64 coef, kt 0..3
__device__ float g_msb[B_ * C_];           // msum d=0 bias
__device__ float g_mom[B_ * I_ * 4];       // S1..S4

__device__ __forceinline__ uint32_t pack2(float a, float b) {
    uint32_t lo = __bfloat16_as_ushort(__float2bfloat16(a));
    uint32_t hi = __bfloat16_as_ushort(__float2bfloat16(b));
    return lo | (hi << 16);
}

__device__ __forceinline__ float bred(float v) {
    __shared__ float sh[8];
    #pragma unroll
    for (int o = 16; o; o >>= 1) v += __shfl_xor_sync(0xffffffffu, v, o);
    __syncthreads();
    if ((threadIdx.x & 31) == 0) sh[threadIdx.x >> 5] = v;
    __syncthreads();
    float r = 0.f;
    #pragma unroll
    for (int j = 0; j < 8; ++j) r += sh[j];
    return r;
}

__device__ __forceinline__ void mma16816(float* d, uint32_t a0, uint32_t a1,
                                         uint32_t a2, uint32_t a3,
                                         uint32_t b0, uint32_t b1) {
    asm volatile(
        "mma.sync.aligned.m16n8k16.row.col.f32.bf16.bf16.f32 "
        "{%0,%1,%2,%3}, {%4,%5,%6,%7}, {%8,%9}, {%0,%1,%2,%3};\n"
        : "+f"(d[0]), "+f"(d[1]), "+f"(d[2]), "+f"(d[3])
        : "r"(a0), "r"(a1), "r"(a2), "r"(a3), "r"(b0), "r"(b1));
}

// ---------------- pack Wf/Wo into fragment layout -----------------
__global__ void k_pack(const float* __restrict__ Wf, const float* __restrict__ Wo) {
    int gid = blockIdx.x * blockDim.x + threadIdx.x;
    if (gid >= 16 * 16 * 32) return;
    int lane = gid & 31, tile = gid >> 5;
    int mt = tile >> 4, kt = tile & 15;
    uint32_t wf[4], wo[4];
    #pragma unroll
    for (int rg = 0; rg < 4; ++rg) {
        int rr = (rg & 1) * 8 + (lane >> 2);
        int kc = (rg >> 1) * 8 + (lane & 3) * 2;
        int m = mt * 16 + rr, k = kt * 16 + kc;
        wf[rg] = pack2(Wf[m * C_ + k], Wf[m * C_ + k + 1]);
        wo[rg] = pack2(Wo[m * C_ + k], Wo[m * C_ + k + 1]);
    }
    g_pWf[gid] = make_uint4(wf[0], wf[1], wf[2], wf[3]);
    g_pWo[gid] = make_uint4(wo[0], wo[1], wo[2], wo[3]);
}

// ---------------- mask moments: one block per (b,i) -----------------
__global__ void k_moments(const float* __restrict__ masks) {
    int bi = blockIdx.x;
    const float* mp = masks + (size_t)bi * P_;
    float s1 = 0.f, s2 = 0.f, s3 = 0.f, s4 = 0.f;
    for (int p = threadIdx.x; p < P_; p += NT) {
        float m = mp[p], m2 = m * m;
        s1 += m; s2 += m2; s3 += m2 * m; s4 += m2 * m2;
    }
    s1 = bred(s1); s2 = bred(s2); s3 = bred(s3); s4 = bred(s4);
    if (threadIdx.x == 0) {
        g_mom[bi * 4 + 0] = s1; g_mom[bi * 4 + 1] = s2;
        g_mom[bi * 4 + 2] = s3; g_mom[bi * 4 + 3] = s4;
    }
}

// ---------------- Z, alpha, packed coef, msum bias -----------------
__global__ void k_coef(const float* __restrict__ Wm, const float* __restrict__ bm) {
    int b = blockIdx.x, c = threadIdx.x;
    int mt = c >> 4, r = c & 15;
    float msb = 0.f;
    uint32_t* pc = (uint32_t*)g_pCf;
    for (int i = 0; i < I_; ++i) {
        float S1 = g_mom[(b * I_ + i) * 4 + 0];
        float S2 = g_mom[(b * I_ + i) * 4 + 1];
        float S3 = g_mom[(b * I_ + i) * 4 + 2];
        float S4 = g_mom[(b * I_ + i) * 4 + 3];
        float w = Wm[i * C_ + c];
        float eb = __expf(bm[i * C_ + c]);
        float w2 = w * w;
        float zc = eb * ((float)P_ + w * S1 + 0.5f * w2 * S2 +
                         (0.166666667f * w2 * w) * S3 +
                         (0.0416666667f * w2 * w2) * S4);
        float Z = bred(zc);
        float a = eb / Z;
        msb += a;
        float cf[4] = { a * w, a * 0.5f * w2, a * 0.166666667f * w2 * w,
                        a * 0.0416666667f * w2 * w2 };
        int k0 = i * 4;
        #pragma unroll
        for (int h = 0; h < 2; ++h) {
            int kp = k0 + h * 2;
            int kt = kp >> 4, kc = kp & 15;
            int ln = (r & 7) * 4 + ((kc & 7) >> 1);
            int rg = (r >> 3) + 2 * (kc >> 3);
            pc[(((size_t)(b * 16 + mt) * 4 + kt) * 32 + ln) * 4 + rg] =
                pack2(cf[h * 2], cf[h * 2 + 1]);
        }
    }
    g_msb[b * C_ + c] = msb;
}

// ---------------- fused main kernel -----------------
__global__ void __launch_bounds__(NT, 1) k_main(
    const float* __restrict__ x, const float* __restrict__ masks,
    const float* __restrict__ bf, const float* __restrict__ bo,
    const float* __restrict__ gamma, float* __restrict__ out)
{
    extern __shared__ __align__(16) unsigned char smem_raw[];
    __nv_bfloat16* sX = (__nv_bfloat16*)smem_raw;   // [TN][XS]
    __nv_bfloat16* sM = sX + TN * XS;               // [TN][MS]
    __nv_bfloat16* sE = sM + TN * MS;               // [TN][XS]
    const int b = blockIdx.y;
    const int p0 = blockIdx.x * TN;
    const int t = threadIdx.x, lane = t & 31, wrp = t >> 5;
    const int tg = lane & 3, gp = lane >> 2;

    // fill sX: x[b, c, p0+n] -> sX[n][c] (bf16)
    {
        const float* xb = x + (size_t)b * C_ * P_ + p0;
        int n = t & 63, c0 = t >> 6;
        #pragma unroll 8
        for (int it = 0; it < 64; ++it) {
            int c = it * 4 + c0;
            sX[n * XS + c] = __float2bfloat16(__ldg(&xb[(size_t)c * P_ + n]));
        }
    }
    // fill sM: mask powers m^1..m^4 at k = i*4+d'
    {
        int n = t & 63, i0 = t >> 6;
        #pragma unroll
        for (int it = 0; it < 4; ++it) {
            int i = it * 4 + i0;
            float m = __ldg(&masks[(size_t)(b * I_ + i) * P_ + p0 + n]);
            float m2 = m * m;
            __nv_bfloat16* d = sM + n * MS + i * 4;
            d[0] = __float2bfloat16(m);
            d[1] = __float2bfloat16(m2);
            d[2] = __float2bfloat16(m2 * m);
            d[3] = __float2bfloat16(m2 * m2);
        }
    }
    __syncthreads();

    const int mt0 = wrp * 2;  // warp owns rows [wrp*32, wrp*32+32)

    // ---- GEMM2: msum (kept in registers) ----
    float ms[2][8][4];
    #pragma unroll
    for (int a = 0; a < 2; a++)
        #pragma unroll
        for (int nn = 0; nn < 8; nn++)
            #pragma unroll
            for (int q = 0; q < 4; q++) ms[a][nn][q] = 0.f;
    {
        const uint4* pA = g_pCf + (size_t)(b * 16 + mt0) * 4 * 32;
        #pragma unroll
        for (int kt = 0; kt < 4; ++kt) {
            uint4 A0 = pA[kt * 32 + lane];
            uint4 A1 = pA[(4 + kt) * 32 + lane];
            int krow = kt * 16 + tg * 2;
            #pragma unroll
            for (int nt = 0; nt < 8; ++nt) {
                int n = nt * 8 + gp;
                uint32_t b0 = *(const uint32_t*)(sM + n * MS + krow);
                uint32_t b1 = *(const uint32_t*)(sM + n * MS + krow + 8);
                mma16816(ms[0][nt], A0.x, A0.y, A0.z, A0.w, b0, b1);
                mma16816(ms[1][nt], A1.x, A1.y, A1.z, A1.w, b0, b1);
            }
        }
        const float* mb = g_msb + b * C_;
        #pragma unroll
        for (int a = 0; a < 2; a++) {
            float b0v = __ldg(&mb[(mt0 + a) * 16 + gp]);
            float b1v = __ldg(&mb[(mt0 + a) * 16 + gp + 8]);
            #pragma unroll
            for (int nt = 0; nt < 8; nt++) {
                ms[a][nt][0] += b0v; ms[a][nt][1] += b0v;
                ms[a][nt][2] += b1v; ms[a][nt][3] += b1v;
            }
        }
    }

    // ---- GEMM1: feat = Wf @ x ----
    float ft[2][8][4];
    #pragma unroll
    for (int a = 0; a < 2; a++)
        #pragma unroll
        for (int nn = 0; nn < 8; nn++)
            #pragma unroll
            for (int q = 0; q < 4; q++) ft[a][nn][q] = 0.f;
    {
        #pragma unroll
        for (int kt = 0; kt < 16; ++kt) {
            uint4 A0 = g_pWf[(mt0 * 16 + kt) * 32 + lane];
            uint4 A1 = g_pWf[((mt0 + 1) * 16 + kt) * 32 + lane];
            int krow = kt * 16 + tg * 2;
            #pragma unroll
            for (int nt = 0; nt < 8; ++nt) {
                int n = nt * 8 + gp;
                uint32_t b0 = *(const uint32_t*)(sX + n * XS + krow);
                uint32_t b1 = *(const uint32_t*)(sX + n * XS + krow + 8);
                mma16816(ft[0][nt], A0.x, A0.y, A0.z, A0.w, b0, b1);
                mma16816(ft[1][nt], A1.x, A1.y, A1.z, A1.w, b0, b1);
            }
        }
    }

    // ---- E = (feat + bf) * msum -> sE[n][c] ----
    {
        #pragma unroll
        for (int a = 0; a < 2; a++) {
            int c = (mt0 + a) * 16 + gp;
            float bf0 = __ldg(&bf[c]);
            float bf1 = __ldg(&bf[c + 8]);
            #pragma unroll
            for (int nt = 0; nt < 8; nt++) {
                int n = nt * 8 + tg * 2;
                sE[n * XS + c]           = __float2bfloat16((ft[a][nt][0] + bf0) * ms[a][nt][0]);
                sE[(n + 1) * XS + c]     = __float2bfloat16((ft[a][nt][1] + bf0) * ms[a][nt][1]);
                sE[n * XS + c + 8]       = __float2bfloat16((ft[a][nt][2] + bf1) * ms[a][nt][2]);
                sE[(n + 1) * XS + c + 8] = __float2bfloat16((ft[a][nt][3] + bf1) * ms[a][nt][3]);
            }
        }
    }
    __syncthreads();

    // ---- GEMM3: out = Wo @ E ----
    float oa[2][8][4];
    #pragma unroll
    for (int a = 0; a < 2; a++)
        #pragma unroll
        for (int nn = 0; nn < 8; nn++)
            #pragma unroll
            for (int q = 0; q < 4; q++) oa[a][nn][q] = 0.f;
    {
        #pragma unroll
        for (int kt = 0; kt < 16; ++kt) {
            uint4 A0 = g_pWo[(mt0 * 16 + kt) * 32 + lane];
            uint4 A1 = g_pWo[((mt0 + 1) * 16 + kt) * 32 + lane];
            int krow = kt * 16 + tg * 2;
            #pragma unroll
            for (int nt = 0; nt < 8; ++nt) {
                int n = nt * 8 + gp;
                uint32_t b0 = *(const uint32_t*)(sE + n * XS + krow);
                uint32_t b1 = *(const uint32_t*)(sE + n * XS + krow + 8);
                mma16816(oa[0][nt], A0.x, A0.y, A0.z, A0.w, b0, b1);
                mma16816(oa[1][nt], A1.x, A1.y, A1.z, A1.w, b0, b1);
            }
        }
    }

    // ---- epilogue: out = gamma*oa + gamma*16*bo + x ----
    {
        const float g = __ldg(gamma);
        const float* xb = x + (size_t)b * C_ * P_ + p0;
        float* ob = out + (size_t)b * C_ * P_ + p0;
        #pragma unroll
        for (int a = 0; a < 2; a++) {
            int c = (mt0 + a) * 16 + gp;
            float bo0 = g * 16.f * __ldg(&bo[c]);
            float bo1 = g * 16.f * __ldg(&bo[c + 8]);
            #pragma unroll
            for (int nt = 0; nt < 8; nt++) {
                int n = nt * 8 + tg * 2;
                float2 xv0 = *(const float2*)(xb + (size_t)c * P_ + n);
                float2 r0;
                r0.x = g * oa[a][nt][0] + bo0 + xv0.x;
                r0.y = g * oa[a][nt][1] + bo0 + xv0.y;
                *(float2*)(ob + (size_t)c * P_ + n) = r0;
                float2 xv1 = *(const float2*)(xb + (size_t)(c + 8) * P_ + n);
                float2 r1;
                r1.x = g * oa[a][nt][2] + bo1 + xv1.x;
                r1.y = g * oa[a][nt][3] + bo1 + xv1.y;
                *(float2*)(ob + (size_t)(c + 8) * P_ + n) = r1;
            }
        }
    }
}

extern "C" void kernel_launch(void* const* d_in, const int* in_sizes, int n_in,
                              void* d_out, int out_size) {
    const float* x     = (const float*)d_in[0];
    const float* masks = (const float*)d_in[1];
    const float* Wf    = (const float*)d_in[2];
    const float* bf    = (const float*)d_in[3];
    const float* Wm    = (const float*)d_in[4];
    const float* bm    = (const float*)d_in[5];
    const float* Wo    = (const float*)d_in[6];
    const float* bo    = (const float*)d_in[7];
    const float* gamma = (const float*)d_in[8];
    float* out = (float*)d_out;

    size_t smem = (size_t)(TN * XS + TN * MS + TN * XS) * sizeof(__nv_bfloat16);
    cudaFuncSetAttribute(k_main, cudaFuncAttributeMaxDynamicSharedMemorySize, (int)smem);

    k_pack<<<32, 256>>>(Wf, Wo);
    k_moments<<<B_ * I_, NT>>>(masks);
    k_coef<<<B_, NT>>>(Wm, bm);
    k_main<<<dim3(P_ / TN, B_), NT, smem>>>(x, masks, bf, bo, gamma, out);
}

// round 5
// speedup vs baseline: 1.2119x; 1.2119x over previous
#include <cuda_runtime.h>
#include <cuda_bf16.h>
#include <stdint.h>

#define B_ 8
#define I_ 16
#define C_ 256
#define P_ 4096
#define TN 64      // pixels per CTA
#define XS 264     // smem row stride (bf16) for K=256 operands
#define MS 72      // smem row stride for K=64 operand
#define NT 256

// packed A operands: uint4 per (tile,lane); tile = mt*NKT + kt
__device__ uint4 g_pWf[16 * 16 * 32];
__device__ uint4 g_pWo[16 * 16 * 32];
__device__ uint4 g_pCf[B_ * 16 * 4 * 32];  // per-b 256x64 coef, kt 0..3
__device__ float g_msb[B_ * C_];           // msum d=0 bias
__device__ float g_mom[B_ * I_ * 4];       // S1..S4

__device__ __forceinline__ uint32_t pack2(float a, float b) {
    uint32_t lo = __bfloat16_as_ushort(__float2bfloat16(a));
    uint32_t hi = __bfloat16_as_ushort(__float2bfloat16(b));
    return lo | (hi << 16);
}

__device__ __forceinline__ float bred(float v) {
    __shared__ float sh[8];
    #pragma unroll
    for (int o = 16; o; o >>= 1) v += __shfl_xor_sync(0xffffffffu, v, o);
    __syncthreads();
    if ((threadIdx.x & 31) == 0) sh[threadIdx.x >> 5] = v;
    __syncthreads();
    float r = 0.f;
    #pragma unroll
    for (int j = 0; j < 8; ++j) r += sh[j];
    return r;
}

__device__ __forceinline__ void mma16816(float* d, uint32_t a0, uint32_t a1,
                                         uint32_t a2, uint32_t a3,
                                         uint32_t b0, uint32_t b1) {
    asm volatile(
        "mma.sync.aligned.m16n8k16.row.col.f32.bf16.bf16.f32 "
        "{%0,%1,%2,%3}, {%4,%5,%6,%7}, {%8,%9}, {%0,%1,%2,%3};\n"
        : "+f"(d[0]), "+f"(d[1]), "+f"(d[2]), "+f"(d[3])
        : "r"(a0), "r"(a1), "r"(a2), "r"(a3), "r"(b0), "r"(b1));
}

// ---------------- pack Wf/Wo into fragment layout -----------------
__global__ void k_pack(const float* __restrict__ Wf, const float* __restrict__ Wo) {
    int gid = blockIdx.x * blockDim.x + threadIdx.x;
    if (gid >= 16 * 16 * 32) return;
    int lane = gid & 31, tile = gid >> 5;
    int mt = tile >> 4, kt = tile & 15;
    uint32_t wf[4], wo[4];
    #pragma unroll
    for (int rg = 0; rg < 4; ++rg) {
        int rr = (rg & 1) * 8 + (lane >> 2);
        int kc = (rg >> 1) * 8 + (lane & 3) * 2;
        int m = mt * 16 + rr, k = kt * 16 + kc;
        wf[rg] = pack2(Wf[m * C_ + k], Wf[m * C_ + k + 1]);
        wo[rg] = pack2(Wo[m * C_ + k], Wo[m * C_ + k + 1]);
    }
    g_pWf[gid] = make_uint4(wf[0], wf[1], wf[2], wf[3]);
    g_pWo[gid] = make_uint4(wo[0], wo[1], wo[2], wo[3]);
}

// ---------------- mask moments: one block per (b,i) -----------------
__global__ void k_moments(const float* __restrict__ masks) {
    int bi = blockIdx.x;
    const float* mp = masks + (size_t)bi * P_;
    float s1 = 0.f, s2 = 0.f, s3 = 0.f, s4 = 0.f;
    for (int p = threadIdx.x; p < P_; p += NT) {
        float m = mp[p], m2 = m * m;
        s1 += m; s2 += m2; s3 += m2 * m; s4 += m2 * m2;
    }
    s1 = bred(s1); s2 = bred(s2); s3 = bred(s3); s4 = bred(s4);
    if (threadIdx.x == 0) {
        g_mom[bi * 4 + 0] = s1; g_mom[bi * 4 + 1] = s2;
        g_mom[bi * 4 + 2] = s3; g_mom[bi * 4 + 3] = s4;
    }
}

// ---------------- Z, alpha, packed coef, msum bias -----------------
__global__ void k_coef(const float* __restrict__ Wm, const float* __restrict__ bm) {
    int b = blockIdx.x, c = threadIdx.x;
    int mt = c >> 4, r = c & 15;
    float msb = 0.f;
    uint32_t* pc = (uint32_t*)g_pCf;
    for (int i = 0; i < I_; ++i) {
        float S1 = g_mom[(b * I_ + i) * 4 + 0];
        float S2 = g_mom[(b * I_ + i) * 4 + 1];
        float S3 = g_mom[(b * I_ + i) * 4 + 2];
        float S4 = g_mom[(b * I_ + i) * 4 + 3];
        float w = Wm[i * C_ + c];
        float eb = __expf(bm[i * C_ + c]);
        float w2 = w * w;
        float zc = eb * ((float)P_ + w * S1 + 0.5f * w2 * S2 +
                         (0.166666667f * w2 * w) * S3 +
                         (0.0416666667f * w2 * w2) * S4);
        float Z = bred(zc);
        float a = eb / Z;
        msb += a;
        float cf[4] = { a * w, a * 0.5f * w2, a * 0.166666667f * w2 * w,
                        a * 0.0416666667f * w2 * w2 };
        int k0 = i * 4;
        #pragma unroll
        for (int h = 0; h < 2; ++h) {
            int kp = k0 + h * 2;
            int kt = kp >> 4, kc = kp & 15;
            int ln = (r & 7) * 4 + ((kc & 7) >> 1);
            int rg = (r >> 3) + 2 * (kc >> 3);
            pc[(((size_t)(b * 16 + mt) * 4 + kt) * 32 + ln) * 4 + rg] =
                pack2(cf[h * 2], cf[h * 2 + 1]);
        }
    }
    g_msb[b * C_ + c] = msb;
}

// ---------------- fused main kernel -----------------
__global__ void __launch_bounds__(NT, 2) k_main(
    const float* __restrict__ x, const float* __restrict__ masks,
    const float* __restrict__ bf, const float* __restrict__ bo,
    const float* __restrict__ gamma, float* __restrict__ out)
{
    extern __shared__ __align__(16) unsigned char smem_raw[];
    __nv_bfloat16* sX = (__nv_bfloat16*)smem_raw;   // [TN][XS]; reused as sE
    __nv_bfloat16* sM = sX + TN * XS;               // [TN][MS]
    __nv_bfloat16* sE = sX;                         // overlay (sX dead after GEMM1)
    const int b = blockIdx.y;
    const int p0 = blockIdx.x * TN;
    const int t = threadIdx.x, lane = t & 31, wrp = t >> 5;
    const int tg = lane & 3, gp = lane >> 2;

    // fill sX: x[b, c, p0+n] -> sX[n][c] (bf16)
    {
        const float* xb = x + (size_t)b * C_ * P_ + p0;
        int n = t & 63, c0 = t >> 6;
        #pragma unroll 8
        for (int it = 0; it < 64; ++it) {
            int c = it * 4 + c0;
            sX[n * XS + c] = __float2bfloat16(__ldg(&xb[(size_t)c * P_ + n]));
        }
    }
    // fill sM: mask powers m^1..m^4 at k = i*4+d'
    {
        int n = t & 63, i0 = t >> 6;
        #pragma unroll
        for (int it = 0; it < 4; ++it) {
            int i = it * 4 + i0;
            float m = __ldg(&masks[(size_t)(b * I_ + i) * P_ + p0 + n]);
            float m2 = m * m;
            __nv_bfloat16* d = sM + n * MS + i * 4;
            d[0] = __float2bfloat16(m);
            d[1] = __float2bfloat16(m2);
            d[2] = __float2bfloat16(m2 * m);
            d[3] = __float2bfloat16(m2 * m2);
        }
    }
    __syncthreads();

    const int mt0 = wrp * 2;  // warp owns rows [wrp*32, wrp*32+32)

    float acc[2][8][4];       // single accumulator set, reused 3x

    // ---- GEMM1: feat = Wf @ x ----
    #pragma unroll
    for (int a = 0; a < 2; a++)
        #pragma unroll
        for (int nn = 0; nn < 8; nn++)
            #pragma unroll
            for (int q = 0; q < 4; q++) acc[a][nn][q] = 0.f;
    #pragma unroll 4
    for (int kt = 0; kt < 16; ++kt) {
        uint4 A0 = g_pWf[(mt0 * 16 + kt) * 32 + lane];
        uint4 A1 = g_pWf[((mt0 + 1) * 16 + kt) * 32 + lane];
        int krow = kt * 16 + tg * 2;
        #pragma unroll
        for (int nt = 0; nt < 8; ++nt) {
            int n = nt * 8 + gp;
            uint32_t b0 = *(const uint32_t*)(sX + n * XS + krow);
            uint32_t b1 = *(const uint32_t*)(sX + n * XS + krow + 8);
            mma16816(acc[0][nt], A0.x, A0.y, A0.z, A0.w, b0, b1);
            mma16816(acc[1][nt], A1.x, A1.y, A1.z, A1.w, b0, b1);
        }
    }
    __syncthreads();   // everyone done reading sX; safe to overlay sE

    // ---- store feat + bf into sE (bf16); ft regs die here ----
    #pragma unroll
    for (int a = 0; a < 2; a++) {
        int c = (mt0 + a) * 16 + gp;
        float bf0 = __ldg(&bf[c]);
        float bf1 = __ldg(&bf[c + 8]);
        #pragma unroll
        for (int nt = 0; nt < 8; nt++) {
            int n = nt * 8 + tg * 2;
            sE[n * XS + c]           = __float2bfloat16(acc[a][nt][0] + bf0);
            sE[(n + 1) * XS + c]     = __float2bfloat16(acc[a][nt][1] + bf0);
            sE[n * XS + c + 8]       = __float2bfloat16(acc[a][nt][2] + bf1);
            sE[(n + 1) * XS + c + 8] = __float2bfloat16(acc[a][nt][3] + bf1);
        }
    }

    // ---- GEMM2: msum into acc ----
    #pragma unroll
    for (int a = 0; a < 2; a++)
        #pragma unroll
        for (int nn = 0; nn < 8; nn++)
            #pragma unroll
            for (int q = 0; q < 4; q++) acc[a][nn][q] = 0.f;
    {
        const uint4* pA = g_pCf + (size_t)(b * 16 + mt0) * 4 * 32;
        #pragma unroll
        for (int kt = 0; kt < 4; ++kt) {
            uint4 A0 = pA[kt * 32 + lane];
            uint4 A1 = pA[(4 + kt) * 32 + lane];
            int krow = kt * 16 + tg * 2;
            #pragma unroll
            for (int nt = 0; nt < 8; ++nt) {
                int n = nt * 8 + gp;
                uint32_t b0 = *(const uint32_t*)(sM + n * MS + krow);
                uint32_t b1 = *(const uint32_t*)(sM + n * MS + krow + 8);
                mma16816(acc[0][nt], A0.x, A0.y, A0.z, A0.w, b0, b1);
                mma16816(acc[1][nt], A1.x, A1.y, A1.z, A1.w, b0, b1);
            }
        }
    }

    // ---- RMW: sE *= (msum + msb); same lane owns same (c,n) slots ----
    {
        const float* mb = g_msb + b * C_;
        #pragma unroll
        for (int a = 0; a < 2; a++) {
            int c = (mt0 + a) * 16 + gp;
            float b0v = __ldg(&mb[c]);
            float b1v = __ldg(&mb[c + 8]);
            #pragma unroll
            for (int nt = 0; nt < 8; nt++) {
                int n = nt * 8 + tg * 2;
                float e0 = __bfloat162float(sE[n * XS + c]);
                float e1 = __bfloat162float(sE[(n + 1) * XS + c]);
                float e2 = __bfloat162float(sE[n * XS + c + 8]);
                float e3 = __bfloat162float(sE[(n + 1) * XS + c + 8]);
                sE[n * XS + c]           = __float2bfloat16(e0 * (acc[a][nt][0] + b0v));
                sE[(n + 1) * XS + c]     = __float2bfloat16(e1 * (acc[a][nt][1] + b0v));
                sE[n * XS + c + 8]       = __float2bfloat16(e2 * (acc[a][nt][2] + b1v));
                sE[(n + 1) * XS + c + 8] = __float2bfloat16(e3 * (acc[a][nt][3] + b1v));
            }
        }
    }
    __syncthreads();   // sE complete for all warps

    // ---- GEMM3: out = Wo @ E ----
    #pragma unroll
    for (int a = 0; a < 2; a++)
        #pragma unroll
        for (int nn = 0; nn < 8; nn++)
            #pragma unroll
            for (int q = 0; q < 4; q++) acc[a][nn][q] = 0.f;
    #pragma unroll 4
    for (int kt = 0; kt < 16; ++kt) {
        uint4 A0 = g_pWo[(mt0 * 16 + kt) * 32 + lane];
        uint4 A1 = g_pWo[((mt0 + 1) * 16 + kt) * 32 + lane];
        int krow = kt * 16 + tg * 2;
        #pragma unroll
        for (int nt = 0; nt < 8; ++nt) {
            int n = nt * 8 + gp;
            uint32_t b0 = *(const uint32_t*)(sE + n * XS + krow);
            uint32_t b1 = *(const uint32_t*)(sE + n * XS + krow + 8);
            mma16816(acc[0][nt], A0.x, A0.y, A0.z, A0.w, b0, b1);
            mma16816(acc[1][nt], A1.x, A1.y, A1.z, A1.w, b0, b1);
        }
    }

    // ---- epilogue: out = gamma*acc + gamma*16*bo + x ----
    {
        const float g = __ldg(gamma);
        const float* xb = x + (size_t)b * C_ * P_ + p0;
        float* ob = out + (size_t)b * C_ * P_ + p0;
        #pragma unroll
        for (int a = 0; a < 2; a++) {
            int c = (mt0 + a) * 16 + gp;
            float bo0 = g * 16.f * __ldg(&bo[c]);
            float bo1 = g * 16.f * __ldg(&bo[c + 8]);
            #pragma unroll
            for (int nt = 0; nt < 8; nt++) {
                int n = nt * 8 + tg * 2;
                float2 xv0 = *(const float2*)(xb + (size_t)c * P_ + n);
                float2 r0;
                r0.x = g * acc[a][nt][0] + bo0 + xv0.x;
                r0.y = g * acc[a][nt][1] + bo0 + xv0.y;
                *(float2*)(ob + (size_t)c * P_ + n) = r0;
                float2 xv1 = *(const float2*)(xb + (size_t)(c + 8) * P_ + n);
                float2 r1;
                r1.x = g * acc[a][nt][2] + bo1 + xv1.x;
                r1.y = g * acc[a][nt][3] + bo1 + xv1.y;
                *(float2*)(ob + (size_t)(c + 8) * P_ + n) = r1;
            }
        }
    }
}

extern "C" void kernel_launch(void* const* d_in, const int* in_sizes, int n_in,
                              void* d_out, int out_size) {
    const float* x     = (const float*)d_in[0];
    const float* masks = (const float*)d_in[1];
    const float* Wf    = (const float*)d_in[2];
    const float* bf    = (const float*)d_in[3];
    const float* Wm    = (const float*)d_in[4];
    const float* bm    = (const float*)d_in[5];
    const float* Wo    = (const float*)d_in[6];
    const float* bo    = (const float*)d_in[7];
    const float* gamma = (const float*)d_in[8];
    float* out = (float*)d_out;

    size_t smem = (size_t)(TN * XS + TN * MS) * sizeof(__nv_bfloat16);
    cudaFuncSetAttribute(k_main, cudaFuncAttributeMaxDynamicSharedMemorySize, (int)smem);

    k_pack<<<32, 256>>>(Wf, Wo);
    k_moments<<<B_ * I_, NT>>>(masks);
    k_coef<<<B_, NT>>>(Wm, bm);
    k_main<<<dim3(P_ / TN, B_), NT, smem>>>(x, masks, bf, bo, gamma, out);
}

// round 6
// speedup vs baseline: 1.3421x; 1.1074x over previous
#include <cuda_runtime.h>
#include <cuda_bf16.h>
#include <stdint.h>

#define B_ 8
#define I_ 16
#define C_ 256
#define P_ 4096
#define TN 32      // pixels per CTA
#define XS 40      // smem row stride (elements) for [c][n] / [k][n] tiles (80B = 5 chunks)
#define NT 256

// packed A operands: uint4 per (tile,lane); tile = mt*NKT + kt
__device__ uint4 g_pWf[16 * 16 * 32];
__device__ uint4 g_pWo[16 * 16 * 32];
__device__ uint4 g_pCf[B_ * 16 * 4 * 32];  // per-b 256x64 coef, kt 0..3
__device__ float g_msb[B_ * C_];           // msum d=0 bias
__device__ float g_mom[B_ * I_ * 4];       // S1..S4

__device__ __forceinline__ uint32_t pack2(float a, float b) {
    uint32_t lo = __bfloat16_as_ushort(__float2bfloat16(a));
    uint32_t hi = __bfloat16_as_ushort(__float2bfloat16(b));
    return lo | (hi << 16);
}

__device__ __forceinline__ float bred(float v) {
    __shared__ float sh[8];
    #pragma unroll
    for (int o = 16; o; o >>= 1) v += __shfl_xor_sync(0xffffffffu, v, o);
    __syncthreads();
    if ((threadIdx.x & 31) == 0) sh[threadIdx.x >> 5] = v;
    __syncthreads();
    float r = 0.f;
    #pragma unroll
    for (int j = 0; j < 8; ++j) r += sh[j];
    return r;
}

__device__ __forceinline__ void mma16816(float* d, uint32_t a0, uint32_t a1,
                                         uint32_t a2, uint32_t a3,
                                         uint32_t b0, uint32_t b1) {
    asm volatile(
        "mma.sync.aligned.m16n8k16.row.col.f32.bf16.bf16.f32 "
        "{%0,%1,%2,%3}, {%4,%5,%6,%7}, {%8,%9}, {%0,%1,%2,%3};\n"
        : "+f"(d[0]), "+f"(d[1]), "+f"(d[2]), "+f"(d[3])
        : "r"(a0), "r"(a1), "r"(a2), "r"(a3), "r"(b0), "r"(b1));
}

// x4.trans ldmatrix: 4 8x8 b16 tiles, transposed (row-major [k][n] -> col-major B frags)
__device__ __forceinline__ void ldsm4t(uint32_t& r0, uint32_t& r1,
                                       uint32_t& r2, uint32_t& r3,
                                       const __nv_bfloat16* p) {
    uint32_t a = (uint32_t)__cvta_generic_to_shared(p);
    asm volatile(
        "ldmatrix.sync.aligned.m8n8.x4.trans.shared.b16 {%0,%1,%2,%3}, [%4];\n"
        : "=r"(r0), "=r"(r1), "=r"(r2), "=r"(r3) : "r"(a));
}

// ---------------- prep: mask moments (blocks 0..127) + weight pack (128..159) --
__global__ void k_prep(const float* __restrict__ masks,
                       const float* __restrict__ Wf, const float* __restrict__ Wo) {
    if (blockIdx.x < 128) {
        int bi = blockIdx.x;
        const float* mp = masks + (size_t)bi * P_;
        float s1 = 0.f, s2 = 0.f, s3 = 0.f, s4 = 0.f;
        for (int p = threadIdx.x; p < P_; p += NT) {
            float m = mp[p], m2 = m * m;
            s1 += m; s2 += m2; s3 += m2 * m; s4 += m2 * m2;
        }
        s1 = bred(s1); s2 = bred(s2); s3 = bred(s3); s4 = bred(s4);
        if (threadIdx.x == 0) {
            g_mom[bi * 4 + 0] = s1; g_mom[bi * 4 + 1] = s2;
            g_mom[bi * 4 + 2] = s3; g_mom[bi * 4 + 3] = s4;
        }
    } else {
        int gid = (blockIdx.x - 128) * NT + threadIdx.x;
        int lane = gid & 31, tile = gid >> 5;
        int mt = tile >> 4, kt = tile & 15;
        uint32_t wf[4], wo[4];
        #pragma unroll
        for (int rg = 0; rg < 4; ++rg) {
            int rr = (rg & 1) * 8 + (lane >> 2);
            int kc = (rg >> 1) * 8 + (lane & 3) * 2;
            int m = mt * 16 + rr, k = kt * 16 + kc;
            wf[rg] = pack2(Wf[m * C_ + k], Wf[m * C_ + k + 1]);
            wo[rg] = pack2(Wo[m * C_ + k], Wo[m * C_ + k + 1]);
        }
        g_pWf[gid] = make_uint4(wf[0], wf[1], wf[2], wf[3]);
        g_pWo[gid] = make_uint4(wo[0], wo[1], wo[2], wo[3]);
    }
}

// ---------------- Z, alpha, packed coef, msum bias -----------------
__global__ void k_coef(const float* __restrict__ Wm, const float* __restrict__ bm) {
    int b = blockIdx.x, c = threadIdx.x;
    int mt = c >> 4, r = c & 15;
    float msb = 0.f;
    uint32_t* pc = (uint32_t*)g_pCf;
    for (int i = 0; i < I_; ++i) {
        float S1 = g_mom[(b * I_ + i) * 4 + 0];
        float S2 = g_mom[(b * I_ + i) * 4 + 1];
        float S3 = g_mom[(b * I_ + i) * 4 + 2];
        float S4 = g_mom[(b * I_ + i) * 4 + 3];
        float w = Wm[i * C_ + c];
        float eb = __expf(bm[i * C_ + c]);
        float w2 = w * w;
        float zc = eb * ((float)P_ + w * S1 + 0.5f * w2 * S2 +
                         (0.166666667f * w2 * w) * S3 +
                         (0.0416666667f * w2 * w2) * S4);
        float Z = bred(zc);
        float a = eb / Z;
        msb += a;
        float cf[4] = { a * w, a * 0.5f * w2, a * 0.166666667f * w2 * w,
                        a * 0.0416666667f * w2 * w2 };
        int k0 = i * 4;
        #pragma unroll
        for (int h = 0; h < 2; ++h) {
            int kp = k0 + h * 2;
            int kt = kp >> 4, kc = kp & 15;
            int ln = (r & 7) * 4 + ((kc & 7) >> 1);
            int rg = (r >> 3) + 2 * (kc >> 3);
            pc[(((size_t)(b * 16 + mt) * 4 + kt) * 32 + ln) * 4 + rg] =
                pack2(cf[h * 2], cf[h * 2 + 1]);
        }
    }
    g_msb[b * C_ + c] = msb;
}

// ---------------- fused main kernel -----------------
__global__ void __launch_bounds__(NT, 3) k_main(
    const float* __restrict__ x, const float* __restrict__ masks,
    const float* __restrict__ bf, const float* __restrict__ bo,
    const float* __restrict__ gamma, float* __restrict__ out)
{
    extern __shared__ __align__(16) unsigned char smem_raw[];
    __nv_bfloat16* sX = (__nv_bfloat16*)smem_raw;   // [C_][XS] (row c, n contiguous); reused as sE
    __nv_bfloat16* sM = sX + C_ * XS;               // [64][XS] (row k=i*4+d, n contiguous)
    __nv_bfloat16* sE = sX;
    const int b = blockIdx.y;
    const int p0 = blockIdx.x * TN;
    const int t = threadIdx.x, lane = t & 31, wrp = t >> 5;
    const int tg = lane & 3, gp = lane >> 2;

    // fill sX: x[b, c, p0+2np..+1] -> sX[c][2np] (bf16x2, STS.32, conflict-light)
    {
        const float* xb = x + (size_t)b * C_ * P_ + p0;
        int np = t & 15, c0 = t >> 4;
        #pragma unroll 4
        for (int it = 0; it < 16; ++it) {
            int c = it * 16 + c0;
            float2 v = *(const float2*)(xb + (size_t)c * P_ + 2 * np);
            *(uint32_t*)(sX + c * XS + 2 * np) = pack2(v.x, v.y);
        }
    }
    // fill sM: row k=i*4+d holds m^{d+1} for pixel n
    {
        int n = t & 31, i0 = t >> 5;
        #pragma unroll
        for (int it = 0; it < 2; ++it) {
            int i = it * 8 + i0;
            float m = __ldg(&masks[(size_t)(b * I_ + i) * P_ + p0 + n]);
            float m2 = m * m;
            sM[(i * 4 + 0) * XS + n] = __float2bfloat16(m);
            sM[(i * 4 + 1) * XS + n] = __float2bfloat16(m2);
            sM[(i * 4 + 2) * XS + n] = __float2bfloat16(m2 * m);
            sM[(i * 4 + 3) * XS + n] = __float2bfloat16(m2 * m2);
        }
    }
    __syncthreads();

    const int mt0 = wrp * 2;  // warp owns rows [wrp*32, wrp*32+32)
    // ldmatrix lane address components (within a k-16 x n-16 block):
    const int lr = lane & 7;                 // row within 8
    const int lk8 = ((lane >> 3) & 1) * 8;   // +8 k for b1 matrices
    const int lnt = (lane >> 4);             // 0/1: which nt of the pair

    float acc[2][4][4];

    // ---- GEMM1: feat = Wf @ x ----
    #pragma unroll
    for (int a = 0; a < 2; a++)
        #pragma unroll
        for (int nn = 0; nn < 4; nn++)
            #pragma unroll
            for (int q = 0; q < 4; q++) acc[a][nn][q] = 0.f;
    #pragma unroll 2
    for (int kt = 0; kt < 16; ++kt) {
        uint4 A0 = g_pWf[(mt0 * 16 + kt) * 32 + lane];
        uint4 A1 = g_pWf[((mt0 + 1) * 16 + kt) * 32 + lane];
        const __nv_bfloat16* pb = sX + (kt * 16 + lr + lk8) * XS;
        #pragma unroll
        for (int ntp = 0; ntp < 2; ++ntp) {
            uint32_t b0, b1, b2, b3;
            ldsm4t(b0, b1, b2, b3, pb + (ntp * 2 + lnt) * 8);
            mma16816(acc[0][ntp * 2],     A0.x, A0.y, A0.z, A0.w, b0, b1);
            mma16816(acc[1][ntp * 2],     A1.x, A1.y, A1.z, A1.w, b0, b1);
            mma16816(acc[0][ntp * 2 + 1], A0.x, A0.y, A0.z, A0.w, b2, b3);
            mma16816(acc[1][ntp * 2 + 1], A1.x, A1.y, A1.z, A1.w, b2, b3);
        }
    }
    __syncthreads();   // all warps done reading sX; safe to overlay sE

    // ---- store feat + bf into sE[c][n] (bf16x2 along n) ----
    #pragma unroll
    for (int a = 0; a < 2; a++) {
        int c = (mt0 + a) * 16 + gp;
        float bf0 = __ldg(&bf[c]);
        float bf1 = __ldg(&bf[c + 8]);
        #pragma unroll
        for (int nt = 0; nt < 4; nt++) {
            int n = nt * 8 + tg * 2;
            *(uint32_t*)(sE + c * XS + n) =
                pack2(acc[a][nt][0] + bf0, acc[a][nt][1] + bf0);
            *(uint32_t*)(sE + (c + 8) * XS + n) =
                pack2(acc[a][nt][2] + bf1, acc[a][nt][3] + bf1);
        }
    }

    // ---- GEMM2: msum ----
    #pragma unroll
    for (int a = 0; a < 2; a++)
        #pragma unroll
        for (int nn = 0; nn < 4; nn++)
            #pragma unroll
            for (int q = 0; q < 4; q++) acc[a][nn][q] = 0.f;
    {
        const uint4* pA = g_pCf + (size_t)(b * 16 + mt0) * 4 * 32;
        #pragma unroll
        for (int kt = 0; kt < 4; ++kt) {
            uint4 A0 = pA[kt * 32 + lane];
            uint4 A1 = pA[(4 + kt) * 32 + lane];
            const __nv_bfloat16* pb = sM + (kt * 16 + lr + lk8) * XS;
            #pragma unroll
            for (int ntp = 0; ntp < 2; ++ntp) {
                uint32_t b0, b1, b2, b3;
                ldsm4t(b0, b1, b2, b3, pb + (ntp * 2 + lnt) * 8);
                mma16816(acc[0][ntp * 2],     A0.x, A0.y, A0.z, A0.w, b0, b1);
                mma16816(acc[1][ntp * 2],     A1.x, A1.y, A1.z, A1.w, b0, b1);
                mma16816(acc[0][ntp * 2 + 1], A0.x, A0.y, A0.z, A0.w, b2, b3);
                mma16816(acc[1][ntp * 2 + 1], A1.x, A1.y, A1.z, A1.w, b2, b3);
            }
        }
    }

    // ---- RMW: sE *= (msum + msb); same lane owns same (c,n) slots ----
    {
        const float* mb = g_msb + b * C_;
        #pragma unroll
        for (int a = 0; a < 2; a++) {
            int c = (mt0 + a) * 16 + gp;
            float b0v = __ldg(&mb[c]);
            float b1v = __ldg(&mb[c + 8]);
            #pragma unroll
            for (int nt = 0; nt < 4; nt++) {
                int n = nt * 8 + tg * 2;
                uint32_t e01 = *(uint32_t*)(sE + c * XS + n);
                uint32_t e23 = *(uint32_t*)(sE + (c + 8) * XS + n);
                float e0 = __bfloat162float(__ushort_as_bfloat16((unsigned short)(e01 & 0xffff)));
                float e1 = __bfloat162float(__ushort_as_bfloat16((unsigned short)(e01 >> 16)));
                float e2 = __bfloat162float(__ushort_as_bfloat16((unsigned short)(e23 & 0xffff)));
                float e3 = __bfloat162float(__ushort_as_bfloat16((unsigned short)(e23 >> 16)));
                *(uint32_t*)(sE + c * XS + n) =
                    pack2(e0 * (acc[a][nt][0] + b0v), e1 * (acc[a][nt][1] + b0v));
                *(uint32_t*)(sE + (c + 8) * XS + n) =
                    pack2(e2 * (acc[a][nt][2] + b1v), e3 * (acc[a][nt][3] + b1v));
            }
        }
    }
    __syncthreads();   // sE complete for all warps

    // ---- GEMM3: out = Wo @ E ----
    #pragma unroll
    for (int a = 0; a < 2; a++)
        #pragma unroll
        for (int nn = 0; nn < 4; nn++)
            #pragma unroll
            for (int q = 0; q < 4; q++) acc[a][nn][q] = 0.f;
    #pragma unroll 2
    for (int kt = 0; kt < 16; ++kt) {
        uint4 A0 = g_pWo[(mt0 * 16 + kt) * 32 + lane];
        uint4 A1 = g_pWo[((mt0 + 1) * 16 + kt) * 32 + lane];
        const __nv_bfloat16* pb = sE + (kt * 16 + lr + lk8) * XS;
        #pragma unroll
        for (int ntp = 0; ntp < 2; ++ntp) {
            uint32_t b0, b1, b2, b3;
            ldsm4t(b0, b1, b2, b3, pb + (ntp * 2 + lnt) * 8);
            mma16816(acc[0][ntp * 2],     A0.x, A0.y, A0.z, A0.w, b0, b1);
            mma16816(acc[1][ntp * 2],     A1.x, A1.y, A1.z, A1.w, b0, b1);
            mma16816(acc[0][ntp * 2 + 1], A0.x, A0.y, A0.z, A0.w, b2, b3);
            mma16816(acc[1][ntp * 2 + 1], A1.x, A1.y, A1.z, A1.w, b2, b3);
        }
    }

    // ---- epilogue: out = gamma*acc + gamma*16*bo + x ----
    {
        const float g = __ldg(gamma);
        const float* xb = x + (size_t)b * C_ * P_ + p0;
        float* ob = out + (size_t)b * C_ * P_ + p0;
        #pragma unroll
        for (int a = 0; a < 2; a++) {
            int c = (mt0 + a) * 16 + gp;
            float bo0 = g * 16.f * __ldg(&bo[c]);
            float bo1 = g * 16.f * __ldg(&bo[c + 8]);
            #pragma unroll
            for (int nt = 0; nt < 4; nt++) {
                int n = nt * 8 + tg * 2;
                float2 xv0 = *(const float2*)(xb + (size_t)c * P_ + n);
                float2 r0;
                r0.x = g * acc[a][nt][0] + bo0 + xv0.x;
                r0.y = g * acc[a][nt][1] + bo0 + xv0.y;
                *(float2*)(ob + (size_t)c * P_ + n) = r0;
                float2 xv1 = *(const float2*)(xb + (size_t)(c + 8) * P_ + n);
                float2 r1;
                r1.x = g * acc[a][nt][2] + bo1 + xv1.x;
                r1.y = g * acc[a][nt][3] + bo1 + xv1.y;
                *(float2*)(ob + (size_t)(c + 8) * P_ + n) = r1;
            }
        }
    }
}

extern "C" void kernel_launch(void* const* d_in, const int* in_sizes, int n_in,
                              void* d_out, int out_size) {
    const float* x     = (const float*)d_in[0];
    const float* masks = (const float*)d_in[1];
    const float* Wf    = (const float*)d_in[2];
    const float* bf    = (const float*)d_in[3];
    const float* Wm    = (const float*)d_in[4];
    const float* bm    = (const float*)d_in[5];
    const float* Wo    = (const float*)d_in[6];
    const float* bo    = (const float*)d_in[7];
    const float* gamma = (const float*)d_in[8];
    float* out = (float*)d_out;

    size_t smem = (size_t)(C_ * XS + 64 * XS) * sizeof(__nv_bfloat16);  // 25.6 KB
    cudaFuncSetAttribute(k_main, cudaFuncAttributeMaxDynamicSharedMemorySize, (int)smem);

    k_prep<<<160, NT>>>(masks, Wf, Wo);
    k_coef<<<B_, NT>>>(Wm, bm);
    k_main<<<dim3(P_ / TN, B_), NT, smem>>>(x, masks, bf, bo, gamma, out);
}

// round 7
// speedup vs baseline: 1.7510x; 1.3047x over previous
#include <cuda_runtime.h>
#include <cuda_bf16.h>
#include <stdint.h>

#define B_ 8
#define I_ 16
#define C_ 256
#define P_ 4096
#define TN 32      // pixels per CTA
#define XS 40      // smem row stride (elements) for [c][n]/[k][n] tiles
#define NT 256

__device__ uint4 g_pWf[16 * 16 * 32];
__device__ uint4 g_pWo[16 * 16 * 32];
__device__ uint4 g_pCf[B_ * 16 * 4 * 32];
__device__ float g_msb[B_ * C_];
__device__ float g_momp[B_ * I_ * 4 * 4];   // [bi][part][d] partial moments

__device__ __forceinline__ uint32_t pack2(float a, float b) {
    uint32_t lo = __bfloat16_as_ushort(__float2bfloat16(a));
    uint32_t hi = __bfloat16_as_ushort(__float2bfloat16(b));
    return lo | (hi << 16);
}

__device__ __forceinline__ void mma16816(float* d, uint32_t a0, uint32_t a1,
                                         uint32_t a2, uint32_t a3,
                                         uint32_t b0, uint32_t b1) {
    asm volatile(
        "mma.sync.aligned.m16n8k16.row.col.f32.bf16.bf16.f32 "
        "{%0,%1,%2,%3}, {%4,%5,%6,%7}, {%8,%9}, {%0,%1,%2,%3};\n"
        : "+f"(d[0]), "+f"(d[1]), "+f"(d[2]), "+f"(d[3])
        : "r"(a0), "r"(a1), "r"(a2), "r"(a3), "r"(b0), "r"(b1));
}

__device__ __forceinline__ void ldsm4t(uint32_t& r0, uint32_t& r1,
                                       uint32_t& r2, uint32_t& r3,
                                       const __nv_bfloat16* p) {
    uint32_t a = (uint32_t)__cvta_generic_to_shared(p);
    asm volatile(
        "ldmatrix.sync.aligned.m8n8.x4.trans.shared.b16 {%0,%1,%2,%3}, [%4];\n"
        : "=r"(r0), "=r"(r1), "=r"(r2), "=r"(r3) : "r"(a));
}

// ---- prep: moment partials (blocks 0..511) + weight pack (512..543) ----
__global__ void k_prep(const float* __restrict__ masks,
                       const float* __restrict__ Wf, const float* __restrict__ Wo) {
    if (blockIdx.x < 512) {
        int bi = blockIdx.x >> 2, part = blockIdx.x & 3;
        float4 v = *(const float4*)(masks + (size_t)bi * P_ + part * 1024 + threadIdx.x * 4);
        float s1 = v.x + v.y + v.z + v.w;
        float s2 = v.x*v.x + v.y*v.y + v.z*v.z + v.w*v.w;
        float s3 = v.x*v.x*v.x + v.y*v.y*v.y + v.z*v.z*v.z + v.w*v.w*v.w;
        float s4 = (v.x*v.x)*(v.x*v.x) + (v.y*v.y)*(v.y*v.y) +
                   (v.z*v.z)*(v.z*v.z) + (v.w*v.w)*(v.w*v.w);
        #pragma unroll
        for (int o = 16; o; o >>= 1) {
            s1 += __shfl_xor_sync(0xffffffffu, s1, o);
            s2 += __shfl_xor_sync(0xffffffffu, s2, o);
            s3 += __shfl_xor_sync(0xffffffffu, s3, o);
            s4 += __shfl_xor_sync(0xffffffffu, s4, o);
        }
        __shared__ float sh[8][4];
        int wrp = threadIdx.x >> 5;
        if ((threadIdx.x & 31) == 0) {
            sh[wrp][0] = s1; sh[wrp][1] = s2; sh[wrp][2] = s3; sh[wrp][3] = s4;
        }
        __syncthreads();
        if (threadIdx.x < 4) {
            float r = 0.f;
            #pragma unroll
            for (int w = 0; w < 8; ++w) r += sh[w][threadIdx.x];
            g_momp[(bi * 4 + part) * 4 + threadIdx.x] = r;
        }
    } else {
        int gid = (blockIdx.x - 512) * NT + threadIdx.x;
        int lane = gid & 31, tile = gid >> 5;
        int mt = tile >> 4, kt = tile & 15;
        uint32_t wf[4], wo[4];
        #pragma unroll
        for (int rg = 0; rg < 4; ++rg) {
            int rr = (rg & 1) * 8 + (lane >> 2);
            int kc = (rg >> 1) * 8 + (lane & 3) * 2;
            int m = mt * 16 + rr, k = kt * 16 + kc;
            wf[rg] = pack2(Wf[m * C_ + k], Wf[m * C_ + k + 1]);
            wo[rg] = pack2(Wo[m * C_ + k], Wo[m * C_ + k + 1]);
        }
        g_pWf[gid] = make_uint4(wf[0], wf[1], wf[2], wf[3]);
        g_pWo[gid] = make_uint4(wo[0], wo[1], wo[2], wo[3]);
    }
}

// ---- Z, alpha, packed coef, msum bias (batched reductions) ----
__global__ void k_coef(const float* __restrict__ Wm, const float* __restrict__ bm) {
    __shared__ float sS[I_][4];      // moments per i
    __shared__ float red[I_][264];   // zc rows for batched reduce
    __shared__ float sZ[I_];
    int b = blockIdx.x, c = threadIdx.x;

    if (c < 64) {
        int i = c >> 2, d = c & 3;
        float r = 0.f;
        #pragma unroll
        for (int p = 0; p < 4; ++p) r += g_momp[((b * I_ + i) * 4 + p) * 4 + d];
        sS[i][d] = r;
    }
    __syncthreads();

    // pass 1: zc rows
    #pragma unroll
    for (int i = 0; i < I_; ++i) {
        float w = Wm[i * C_ + c];
        float eb = __expf(bm[i * C_ + c]);
        float w2 = w * w;
        red[i][c] = eb * ((float)P_ + w * sS[i][0] + 0.5f * w2 * sS[i][1] +
                          (0.166666667f * w2 * w) * sS[i][2] +
                          (0.0416666667f * w2 * w2) * sS[i][3]);
    }
    __syncthreads();

    // batched reduce: warp w handles i = 2w, 2w+1
    {
        int wrp = c >> 5, lane = c & 31;
        #pragma unroll
        for (int h = 0; h < 2; ++h) {
            int i = wrp * 2 + h;
            float v = 0.f;
            #pragma unroll
            for (int j = 0; j < 8; ++j) v += red[i][lane + j * 32];
            #pragma unroll
            for (int o = 16; o; o >>= 1) v += __shfl_xor_sync(0xffffffffu, v, o);
            if (lane == 0) sZ[i] = v;
        }
    }
    __syncthreads();

    // pass 2: coef pack
    int mt = c >> 4, r = c & 15;
    float msb = 0.f;
    uint32_t* pc = (uint32_t*)g_pCf;
    #pragma unroll
    for (int i = 0; i < I_; ++i) {
        float w = Wm[i * C_ + c];
        float eb = __expf(bm[i * C_ + c]);
        float w2 = w * w;
        float a = eb / sZ[i];
        msb += a;
        float cf[4] = { a * w, a * 0.5f * w2, a * 0.166666667f * w2 * w,
                        a * 0.0416666667f * w2 * w2 };
        int k0 = i * 4;
        #pragma unroll
        for (int h = 0; h < 2; ++h) {
            int kp = k0 + h * 2;
            int kt = kp >> 4, kc = kp & 15;
            int ln = (r & 7) * 4 + ((kc & 7) >> 1);
            int rg = (r >> 3) + 2 * (kc >> 3);
            pc[(((size_t)(b * 16 + mt) * 4 + kt) * 32 + ln) * 4 + rg] =
                pack2(cf[h * 2], cf[h * 2 + 1]);
        }
    }
    g_msb[b * C_ + c] = msb;
}

// ---------------- fused main kernel -----------------
__global__ void __launch_bounds__(NT, 3) k_main(
    const float* __restrict__ x, const float* __restrict__ masks,
    const float* __restrict__ bf, const float* __restrict__ bo,
    const float* __restrict__ gamma, float* __restrict__ out)
{
    extern __shared__ __align__(16) unsigned char smem_raw[];
    __nv_bfloat16* sX = (__nv_bfloat16*)smem_raw;   // [C_][XS]; reused as sE
    __nv_bfloat16* sM = sX + C_ * XS;               // [64][XS]
    __nv_bfloat16* sE = sX;
    const int b = blockIdx.y;
    const int p0 = blockIdx.x * TN;
    const int t = threadIdx.x, lane = t & 31, wrp = t >> 5;
    const int tg = lane & 3, gp = lane >> 2;

    {
        const float* xb = x + (size_t)b * C_ * P_ + p0;
        int np = t & 15, c0 = t >> 4;
        #pragma unroll 4
        for (int it = 0; it < 16; ++it) {
            int c = it * 16 + c0;
            float2 v = *(const float2*)(xb + (size_t)c * P_ + 2 * np);
            *(uint32_t*)(sX + c * XS + 2 * np) = pack2(v.x, v.y);
        }
    }
    {
        int n = t & 31, i0 = t >> 5;
        #pragma unroll
        for (int it = 0; it < 2; ++it) {
            int i = it * 8 + i0;
            float m = __ldg(&masks[(size_t)(b * I_ + i) * P_ + p0 + n]);
            float m2 = m * m;
            sM[(i * 4 + 0) * XS + n] = __float2bfloat16(m);
            sM[(i * 4 + 1) * XS + n] = __float2bfloat16(m2);
            sM[(i * 4 + 2) * XS + n] = __float2bfloat16(m2 * m);
            sM[(i * 4 + 3) * XS + n] = __float2bfloat16(m2 * m2);
        }
    }
    __syncthreads();

    const int mt0 = wrp * 2;
    const int lr = lane & 7;
    const int lk8 = ((lane >> 3) & 1) * 8;
    const int lnt = (lane >> 4);

    float acc[2][4][4];

    // ---- GEMM1: feat = Wf @ x (A prefetch double-buffered) ----
    #pragma unroll
    for (int a = 0; a < 2; a++)
        #pragma unroll
        for (int nn = 0; nn < 4; nn++)
            #pragma unroll
            for (int q = 0; q < 4; q++) acc[a][nn][q] = 0.f;
    {
        uint4 A0 = g_pWf[(mt0 * 16) * 32 + lane];
        uint4 A1 = g_pWf[((mt0 + 1) * 16) * 32 + lane];
        #pragma unroll
        for (int kt = 0; kt < 16; ++kt) {
            uint4 N0, N1;
            if (kt < 15) {
                N0 = g_pWf[(mt0 * 16 + kt + 1) * 32 + lane];
                N1 = g_pWf[((mt0 + 1) * 16 + kt + 1) * 32 + lane];
            }
            const __nv_bfloat16* pb = sX + (kt * 16 + lr + lk8) * XS;
            #pragma unroll
            for (int ntp = 0; ntp < 2; ++ntp) {
                uint32_t b0, b1, b2, b3;
                ldsm4t(b0, b1, b2, b3, pb + (ntp * 2 + lnt) * 8);
                mma16816(acc[0][ntp * 2],     A0.x, A0.y, A0.z, A0.w, b0, b1);
                mma16816(acc[1][ntp * 2],     A1.x, A1.y, A1.z, A1.w, b0, b1);
                mma16816(acc[0][ntp * 2 + 1], A0.x, A0.y, A0.z, A0.w, b2, b3);
                mma16816(acc[1][ntp * 2 + 1], A1.x, A1.y, A1.z, A1.w, b2, b3);
            }
            if (kt < 15) { A0 = N0; A1 = N1; }
        }
    }
    __syncthreads();

    // ---- store feat + bf into sE ----
    #pragma unroll
    for (int a = 0; a < 2; a++) {
        int c = (mt0 + a) * 16 + gp;
        float bf0 = __ldg(&bf[c]);
        float bf1 = __ldg(&bf[c + 8]);
        #pragma unroll
        for (int nt = 0; nt < 4; nt++) {
            int n = nt * 8 + tg * 2;
            *(uint32_t*)(sE + c * XS + n) =
                pack2(acc[a][nt][0] + bf0, acc[a][nt][1] + bf0);
            *(uint32_t*)(sE + (c + 8) * XS + n) =
                pack2(acc[a][nt][2] + bf1, acc[a][nt][3] + bf1);
        }
    }

    // ---- GEMM2: msum ----
    #pragma unroll
    for (int a = 0; a < 2; a++)
        #pragma unroll
        for (int nn = 0; nn < 4; nn++)
            #pragma unroll
            for (int q = 0; q < 4; q++) acc[a][nn][q] = 0.f;
    {
        const uint4* pA = g_pCf + (size_t)(b * 16 + mt0) * 4 * 32;
        #pragma unroll
        for (int kt = 0; kt < 4; ++kt) {
            uint4 A0 = pA[kt * 32 + lane];
            uint4 A1 = pA[(4 + kt) * 32 + lane];
            const __nv_bfloat16* pb = sM + (kt * 16 + lr + lk8) * XS;
            #pragma unroll
            for (int ntp = 0; ntp < 2; ++ntp) {
                uint32_t b0, b1, b2, b3;
                ldsm4t(b0, b1, b2, b3, pb + (ntp * 2 + lnt) * 8);
                mma16816(acc[0][ntp * 2],     A0.x, A0.y, A0.z, A0.w, b0, b1);
                mma16816(acc[1][ntp * 2],     A1.x, A1.y, A1.z, A1.w, b0, b1);
                mma16816(acc[0][ntp * 2 + 1], A0.x, A0.y, A0.z, A0.w, b2, b3);
                mma16816(acc[1][ntp * 2 + 1], A1.x, A1.y, A1.z, A1.w, b2, b3);
            }
        }
    }

    // ---- RMW: sE *= (msum + msb) ----
    {
        const float* mb = g_msb + b * C_;
        #pragma unroll
        for (int a = 0; a < 2; a++) {
            int c = (mt0 + a) * 16 + gp;
            float b0v = __ldg(&mb[c]);
            float b1v = __ldg(&mb[c + 8]);
            #pragma unroll
            for (int nt = 0; nt < 4; nt++) {
                int n = nt * 8 + tg * 2;
                uint32_t e01 = *(uint32_t*)(sE + c * XS + n);
                uint32_t e23 = *(uint32_t*)(sE + (c + 8) * XS + n);
                float e0 = __bfloat162float(__ushort_as_bfloat16((unsigned short)(e01 & 0xffff)));
                float e1 = __bfloat162float(__ushort_as_bfloat16((unsigned short)(e01 >> 16)));
                float e2 = __bfloat162float(__ushort_as_bfloat16((unsigned short)(e23 & 0xffff)));
                float e3 = __bfloat162float(__ushort_as_bfloat16((unsigned short)(e23 >> 16)));
                *(uint32_t*)(sE + c * XS + n) =
                    pack2(e0 * (acc[a][nt][0] + b0v), e1 * (acc[a][nt][1] + b0v));
                *(uint32_t*)(sE + (c + 8) * XS + n) =
                    pack2(e2 * (acc[a][nt][2] + b1v), e3 * (acc[a][nt][3] + b1v));
            }
        }
    }
    __syncthreads();

    // ---- GEMM3: out = Wo @ E (A prefetch double-buffered) ----
    #pragma unroll
    for (int a = 0; a < 2; a++)
        #pragma unroll
        for (int nn = 0; nn < 4; nn++)
            #pragma unroll
            for (int q = 0; q < 4; q++) acc[a][nn][q] = 0.f;
    {
        uint4 A0 = g_pWo[(mt0 * 16) * 32 + lane];
        uint4 A1 = g_pWo[((mt0 + 1) * 16) * 32 + lane];
        #pragma unroll
        for (int kt = 0; kt < 16; ++kt) {
            uint4 N0, N1;
            if (kt < 15) {
                N0 = g_pWo[(mt0 * 16 + kt + 1) * 32 + lane];
                N1 = g_pWo[((mt0 + 1) * 16 + kt + 1) * 32 + lane];
            }
            const __nv_bfloat16* pb = sE + (kt * 16 + lr + lk8) * XS;
            #pragma unroll
            for (int ntp = 0; ntp < 2; ++ntp) {
                uint32_t b0, b1, b2, b3;
                ldsm4t(b0, b1, b2, b3, pb + (ntp * 2 + lnt) * 8);
                mma16816(acc[0][ntp * 2],     A0.x, A0.y, A0.z, A0.w, b0, b1);
                mma16816(acc[1][ntp * 2],     A1.x, A1.y, A1.z, A1.w, b0, b1);
                mma16816(acc[0][ntp * 2 + 1], A0.x, A0.y, A0.z, A0.w, b2, b3);
                mma16816(acc[1][ntp * 2 + 1], A1.x, A1.y, A1.z, A1.w, b2, b3);
            }
            if (kt < 15) { A0 = N0; A1 = N1; }
        }
    }

    // ---- epilogue ----
    {
        const float g = __ldg(gamma);
        const float* xb = x + (size_t)b * C_ * P_ + p0;
        float* ob = out + (size_t)b * C_ * P_ + p0;
        #pragma unroll
        for (int a = 0; a < 2; a++) {
            int c = (mt0 + a) * 16 + gp;
            float bo0 = g * 16.f * __ldg(&bo[c]);
            float bo1 = g * 16.f * __ldg(&bo[c + 8]);
            #pragma unroll
            for (int nt = 0; nt < 4; nt++) {
                int n = nt * 8 + tg * 2;
                float2 xv0 = *(const float2*)(xb + (size_t)c * P_ + n);
                float2 r0;
                r0.x = g * acc[a][nt][0] + bo0 + xv0.x;
                r0.y = g * acc[a][nt][1] + bo0 + xv0.y;
                *(float2*)(ob + (size_t)c * P_ + n) = r0;
                float2 xv1 = *(const float2*)(xb + (size_t)(c + 8) * P_ + n);
                float2 r1;
                r1.x = g * acc[a][nt][2] + bo1 + xv1.x;
                r1.y = g * acc[a][nt][3] + bo1 + xv1.y;
                *(float2*)(ob + (size_t)(c + 8) * P_ + n) = r1;
            }
        }
    }
}

extern "C" void kernel_launch(void* const* d_in, const int* in_sizes, int n_in,
                              void* d_out, int out_size) {
    const float* x     = (const float*)d_in[0];
    const float* masks = (const float*)d_in[1];
    const float* Wf    = (const float*)d_in[2];
    const float* bf    = (const float*)d_in[3];
    const float* Wm    = (const float*)d_in[4];
    const float* bm    = (const float*)d_in[5];
    const float* Wo    = (const float*)d_in[6];
    const float* bo    = (const float*)d_in[7];
    const float* gamma = (const float*)d_in[8];
    float* out = (float*)d_out;

    size_t smem = (size_t)(C_ * XS + 64 * XS) * sizeof(__nv_bfloat16);  // 25.6 KB
    cudaFuncSetAttribute(k_main, cudaFuncAttributeMaxDynamicSharedMemorySize, (int)smem);

    k_prep<<<544, NT>>>(masks, Wf, Wo);
    k_coef<<<B_, NT>>>(Wm, bm);
    k_main<<<dim3(P_ / TN, B_), NT, smem>>>(x, masks, bf, bo, gamma, out);
}